// round 9
// baseline (speedup 1.0000x reference)
#include <cuda_runtime.h>
#include <cstdint>

#define BB 256
#define TT 512
#define II 64
#define HH 512
#define OO 24

#define CLUSTER_NCTAS 8
#define NBLOCKS 128
#define NTHREADS 512

#define BM 16     // batch rows per cluster
#define HC 64     // hidden cols per CTA (rank)

typedef unsigned long long u64;

// Hidden state ping-pong, b-major: g_h[parity][b][h]
__device__ float g_h[2][BB * HH];

// SMEM: Hs[16][128 float4] swizzled (32KB) + Xs[16][64] (4KB)
#define HS_F4 (BM * 128)
#define XS_F  (BM * II)
#define SMEM_BYTES (HS_F4 * 16 + XS_F * 4)   // 36864

#define FFMA2(acc, a, w) \
    asm("fma.rn.f32x2 %0, %1, %2, %0;" : "+l"(acc) : "l"(a), "l"(w))

__device__ __forceinline__ float4 ld_cg_v4(const float4* p) {
    float4 v;
    asm volatile("ld.global.cg.v4.f32 {%0,%1,%2,%3}, [%4];"
                 : "=f"(v.x), "=f"(v.y), "=f"(v.z), "=f"(v.w) : "l"(p) : "memory");
    return v;
}

__global__ void __launch_bounds__(NTHREADS, 1) __cluster_dims__(CLUSTER_NCTAS, 1, 1)
rnn_persistent_kernel(const float* __restrict__ x,
                      const float* __restrict__ W_ih,
                      const float* __restrict__ W_hh,
                      const float* __restrict__ b_ih,
                      const float* __restrict__ b_hh,
                      const float* __restrict__ fc_w,
                      const float* __restrict__ fc_b,
                      float* __restrict__ out)
{
    extern __shared__ float smem[];
    float4* Hs4 = (float4*)smem;              // [b][128 f4], piece-swizzled
    float*  Xs  = smem + HS_F4 * 4;           // [b][64]
    const u64* xq = (const u64*)Xs;

    const int tid  = threadIdx.x;
    const int lane = tid & 31;
    const int warp = tid >> 5;                // 0..15
    const int rank = blockIdx.x & (CLUSTER_NCTAS - 1);
    const int cl   = blockIdx.x >> 3;
    const int b0   = cl * BM;
    const int h0   = rank * HC;
    const int hw   = h0 + 4 * warp;           // warp's 4 h-columns
    const int k0   = lane * 16;               // lane's k-chunk
    const int i0   = lane * 2;                // lane's i-chunk

    // ---- register-resident weights (constant across all timesteps) ----
    u64 whh[4][8];
    u64 wih[4];
    #pragma unroll
    for (int h = 0; h < 4; ++h) {
        const ulonglong2* wrow =
            (const ulonglong2*)&W_hh[(size_t)(hw + h) * HH + k0];
        #pragma unroll
        for (int j = 0; j < 4; ++j) {
            ulonglong2 v = wrow[j];
            whh[h][2 * j]     = v.x;
            whh[h][2 * j + 1] = v.y;
        }
        wih[h] = *(const u64*)&W_ih[(size_t)(hw + h) * II + i0];
    }
    const int h_idx = 2 * (lane & 1) + ((lane >> 1) & 1);   // reduction output map
    const float biasv = b_ih[hw + h_idx] + b_hh[hw + h_idx];

    const float4* x4 = (const float4*)x;

    // ---- prefetch x_0 into registers ----
    const int xb  = tid >> 4;                 // batch row (tid<256)
    const int xi4 = tid & 15;                 // float4 index within row
    float4 xreg;
    if (tid < 256)
        xreg = x4[((size_t)(b0 + xb) * TT + 0) * 16 + xi4];

    for (int t = 0; t < TT; ++t) {
        const float4* gprev4 = (const float4*)g_h[1 - (t & 1)];
        float*        gnew   = g_h[t & 1];

        // ---- commit prefetched x_t to smem ----
        if (tid < 256)
            ((float4*)Xs)[xb * 16 + xi4] = xreg;

        // ---- stage h_{t-1} (coalesced) into swizzled Hs ----
        if (t > 0) {
            #pragma unroll
            for (int n = 0; n < 4; ++n) {
                int idx = tid + n * NTHREADS;
                int b = idx >> 7, p = idx & 127;
                float4 v = ld_cg_v4(gprev4 + (size_t)(b0 + b) * 128 + p);
                Hs4[b * 128 + (p ^ ((p >> 3) & 3))] = v;
            }
        }
        __syncthreads();

        const bool rec = (t > 0);

        #pragma unroll 2
        for (int b = 0; b < BM; ++b) {
            u64 acc0 = 0ull, acc1 = 0ull, acc2 = 0ull, acc3 = 0ull;

            // input projection: one i-pair per lane
            u64 ax = xq[b * 32 + lane];
            FFMA2(acc0, ax, wih[0]);
            FFMA2(acc1, ax, wih[1]);
            FFMA2(acc2, ax, wih[2]);
            FFMA2(acc3, ax, wih[3]);

            // recurrent: 4 swizzled conflict-free LDS.128 per lane
            if (rec) {
                const ulonglong2* hrow = (const ulonglong2*)(Hs4 + b * 128);
                #pragma unroll
                for (int j = 0; j < 4; ++j) {
                    ulonglong2 v = hrow[(lane * 4 + j) ^ ((lane >> 1) & 3)];
                    FFMA2(acc0, v.x, whh[0][2 * j]);
                    FFMA2(acc0, v.y, whh[0][2 * j + 1]);
                    FFMA2(acc1, v.x, whh[1][2 * j]);
                    FFMA2(acc1, v.y, whh[1][2 * j + 1]);
                    FFMA2(acc2, v.x, whh[2][2 * j]);
                    FFMA2(acc2, v.y, whh[2][2 * j + 1]);
                    FFMA2(acc3, v.x, whh[3][2 * j]);
                    FFMA2(acc3, v.y, whh[3][2 * j + 1]);
                }
            }

            // unpack packed (even,odd) partials
            float s0, s1, s2, s3, e;
            asm("mov.b64 {%0,%1}, %2;" : "=f"(s0), "=f"(e) : "l"(acc0)); s0 += e;
            asm("mov.b64 {%0,%1}, %2;" : "=f"(s1), "=f"(e) : "l"(acc1)); s1 += e;
            asm("mov.b64 {%0,%1}, %2;" : "=f"(s2), "=f"(e) : "l"(acc2)); s2 += e;
            asm("mov.b64 {%0,%1}, %2;" : "=f"(s3), "=f"(e) : "l"(acc3)); s3 += e;

            // 6-shfl tree reduction (proven R6 mapping)
            bool o1 = lane & 1;
            float k0_ = o1 ? s2 : s0, k1_ = o1 ? s3 : s1;
            float g0_ = o1 ? s0 : s2, g1_ = o1 ? s1 : s3;
            k0_ += __shfl_xor_sync(0xffffffffu, g0_, 1);
            k1_ += __shfl_xor_sync(0xffffffffu, g1_, 1);
            bool o2 = lane & 2;
            float k_ = o2 ? k1_ : k0_;
            float g_ = o2 ? k0_ : k1_;
            k_ += __shfl_xor_sync(0xffffffffu, g_, 2);
            k_ += __shfl_xor_sync(0xffffffffu, k_, 4);
            k_ += __shfl_xor_sync(0xffffffffu, k_, 8);
            k_ += __shfl_xor_sync(0xffffffffu, k_, 16);

            float r = fmaxf(k_ + biasv, 0.f);
            if (lane < 4)
                gnew[(size_t)(b0 + b) * HH + hw + h_idx] = r;
        }

        // ---- prefetch x_{t+1} (hides under barrier wait) ----
        if (tid < 256 && t + 1 < TT)
            xreg = x4[((size_t)(b0 + xb) * TT + (t + 1)) * 16 + xi4];

        // ---- cluster barrier (release h stores; acquire peers') ----
        asm volatile("fence.acq_rel.cluster;" ::: "memory");
        asm volatile("barrier.cluster.arrive.aligned;" ::: "memory");
        asm volatile("barrier.cluster.wait.aligned;"   ::: "memory");
    }

    // ---- fused FC epilogue ----
    {
        const float4* gl4 = (const float4*)g_h[(TT - 1) & 1];
        #pragma unroll
        for (int n = 0; n < 4; ++n) {
            int idx = tid + n * NTHREADS;
            int b = idx >> 7, p = idx & 127;
            float4 v = ld_cg_v4(gl4 + (size_t)(b0 + b) * 128 + p);
            Hs4[b * 128 + (p ^ ((p >> 3) & 3))] = v;
        }
        __syncthreads();

        if (rank == 0) {
            // warp w owns batch row b0+w; hoist its h pieces to regs
            float4 hp[4];
            #pragma unroll
            for (int i = 0; i < 4; ++i) {
                int p = lane + 32 * i;
                hp[i] = Hs4[warp * 128 + (p ^ ((p >> 3) & 3))];
            }
            #pragma unroll 4
            for (int o = 0; o < OO; ++o) {
                const float4* w4 = (const float4*)(fc_w + (size_t)o * HH);
                float s = 0.f;
                #pragma unroll
                for (int i = 0; i < 4; ++i) {
                    float4 wv = __ldg(&w4[lane + 32 * i]);
                    s = fmaf(hp[i].x, wv.x, s);
                    s = fmaf(hp[i].y, wv.y, s);
                    s = fmaf(hp[i].z, wv.z, s);
                    s = fmaf(hp[i].w, wv.w, s);
                }
                #pragma unroll
                for (int d = 16; d > 0; d >>= 1)
                    s += __shfl_xor_sync(0xffffffffu, s, d);
                if (lane == 0)
                    out[(size_t)(b0 + warp) * OO + o] = s + fc_b[o];
            }
        }
    }
}

extern "C" void kernel_launch(void* const* d_in, const int* in_sizes, int n_in,
                              void* d_out, int out_size)
{
    const float* x    = (const float*)d_in[0];
    const float* W_ih = (const float*)d_in[1];
    const float* W_hh = (const float*)d_in[2];
    const float* b_ih = (const float*)d_in[3];
    const float* b_hh = (const float*)d_in[4];
    const float* fc_w = (const float*)d_in[5];
    const float* fc_b = (const float*)d_in[6];
    int nb = 0;
    for (int i = 0; i < n_in; ++i) {
        const float* p = (const float*)d_in[i];
        switch (in_sizes[i]) {
            case BB * TT * II: x    = p; break;
            case HH * II:      W_ih = p; break;
            case HH * HH:      W_hh = p; break;
            case OO * HH:      fc_w = p; break;
            case OO:           fc_b = p; break;
            case HH:           if (nb++ == 0) b_ih = p; else b_hh = p; break;
            default: break;
        }
    }
    float* out = (float*)d_out;

    cudaFuncSetAttribute(rnn_persistent_kernel,
                         cudaFuncAttributeMaxDynamicSharedMemorySize, SMEM_BYTES);
    rnn_persistent_kernel<<<NBLOCKS, NTHREADS, SMEM_BYTES>>>(
        x, W_ih, W_hh, b_ih, b_hh, fc_w, fc_b, out);
}